// round 14
// baseline (speedup 1.0000x reference)
#include <cuda_runtime.h>
#include <cstdint>
#include <cstddef>

#define Bb 2
#define Ss 2048
#define Ee 1024
#define Hh 16
#define Dd 64
#define E3 3072
#define MM (Bb * Ss)

// Scratch (no allocations allowed anywhere)
__device__ float g_qkv[MM * E3];    // [B,S,3E] = Q|K|V
__device__ float g_attn[MM * Ee];   // [B,S,E]

// fp32 -> tf32 (round-to-nearest) as raw b32
__device__ __forceinline__ unsigned f2tf(float x) {
    unsigned u;
    asm("cvt.rna.tf32.f32 %0, %1;" : "=r"(u) : "f"(x));
    return u;
}

// D(16x8,f32) += A(16x8,tf32) * B(8x8,tf32)
__device__ __forceinline__ void mma_tf32(float* d, const unsigned* a, const unsigned* b) {
    asm("mma.sync.aligned.m16n8k8.row.col.f32.tf32.tf32.f32 "
        "{%0,%1,%2,%3}, {%4,%5,%6,%7}, {%8,%9}, {%0,%1,%2,%3};\n"
        : "+f"(d[0]), "+f"(d[1]), "+f"(d[2]), "+f"(d[3])
        : "r"(a[0]), "r"(a[1]), "r"(a[2]), "r"(a[3]),
          "r"(b[0]), "r"(b[1]));
}

__device__ __forceinline__ void cpa16(void* dst, const void* src) {
    unsigned s = (unsigned)__cvta_generic_to_shared(dst);
    asm volatile("cp.async.cg.shared.global [%0], [%1], 16;" :: "r"(s), "l"(src));
}
__device__ __forceinline__ void cpa_commit() { asm volatile("cp.async.commit_group;"); }
__device__ __forceinline__ void cpa_wait1()  { asm volatile("cp.async.wait_group 1;"); }
__device__ __forceinline__ void cpa_wait0()  { asm volatile("cp.async.wait_group 0;"); }

// ---------------------------------------------------------------------------
// tf32 GEMM (round-6 verified): C = A[MxK] @ W[KxN] + bias
// Block 256 thr (8 warps), tile 128x128, K-step 16, 3-stage cp.async.
// ---------------------------------------------------------------------------
#define ASTR 20
#define BSTR 136
#define ASZ  (128 * ASTR)
#define BSZ  (16 * BSTR)
#define STG  (ASZ + BSZ)
#define SMEM_BYTES (3 * STG * 4)   // 56832 B

__device__ __forceinline__ void tgemm2(
    const float* __restrict__ A, const float* __restrict__ W,
    const float* __restrict__ bias, float* __restrict__ C,
    int N, int K)
{
    extern __shared__ float sh[];

    const int t = threadIdx.x;
    const int lane = t & 31, w = t >> 5;
    const int q = lane & 3, g = lane >> 2;
    const int wm = (w & 1) * 64, wn = (w >> 1) * 32;
    const int brow = blockIdx.y * 128, bcol = blockIdx.x * 128;
    const int nk = K / 16;

    float acc[4][4][4];
#pragma unroll
    for (int i = 0; i < 4; i++)
#pragma unroll
        for (int j = 0; j < 4; j++)
#pragma unroll
            for (int r = 0; r < 4; r++) acc[i][j][r] = 0.f;

    auto stage = [&](int st, int kt) {
        float* As = sh + st * STG;
        float* Bs = As + ASZ;
#pragma unroll
        for (int i = 0; i < 2; i++) {
            int c = t + i * 256;
            int m = c >> 2, k4 = c & 3;
            cpa16(As + m * ASTR + k4 * 4,
                  A + (size_t)(brow + m) * K + kt * 16 + k4 * 4);
        }
#pragma unroll
        for (int i = 0; i < 2; i++) {
            int c = t + i * 256;
            int k = c >> 5, n4 = c & 31;
            cpa16(Bs + k * BSTR + n4 * 4,
                  W + (size_t)(kt * 16 + k) * N + bcol + n4 * 4);
        }
    };

    stage(0, 0); cpa_commit();
    stage(1, 1); cpa_commit();

    for (int kt = 0; kt < nk; kt++) {
        cpa_wait1();
        __syncthreads();
        if (kt + 2 < nk) stage((kt + 2) % 3, kt + 2);
        cpa_commit();

        const float* As = sh + (kt % 3) * STG;
        const float* Bs = As + ASZ;

#pragma unroll
        for (int ks = 0; ks < 2; ks++) {
            unsigned af[4][4], bf[4][2];
#pragma unroll
            for (int mf = 0; mf < 4; mf++) {
                const float* p  = As + (wm + mf * 16 + g) * ASTR + ks * 8;
                const float* p8 = p + 8 * ASTR;
                af[mf][0] = f2tf(p[q]);
                af[mf][1] = f2tf(p8[q]);
                af[mf][2] = f2tf(p[q + 4]);
                af[mf][3] = f2tf(p8[q + 4]);
            }
#pragma unroll
            for (int nf = 0; nf < 4; nf++) {
                const int n = wn + nf * 8 + g;
                bf[nf][0] = f2tf(Bs[(ks * 8 + q) * BSTR + n]);
                bf[nf][1] = f2tf(Bs[(ks * 8 + q + 4) * BSTR + n]);
            }
#pragma unroll
            for (int mf = 0; mf < 4; mf++)
#pragma unroll
                for (int nf = 0; nf < 4; nf++)
                    mma_tf32(acc[mf][nf], af[mf], bf[nf]);
        }
    }

#pragma unroll
    for (int mf = 0; mf < 4; mf++) {
#pragma unroll
        for (int nf = 0; nf < 4; nf++) {
            int r0 = brow + wm + mf * 16 + g;
            int c0 = bcol + wn + nf * 8 + 2 * q;
            float bz0 = bias[c0], bz1 = bias[c0 + 1];
            *(float2*)(C + (size_t)r0 * N + c0) =
                make_float2(acc[mf][nf][0] + bz0, acc[mf][nf][1] + bz1);
            *(float2*)(C + (size_t)(r0 + 8) * N + c0) =
                make_float2(acc[mf][nf][2] + bz0, acc[mf][nf][3] + bz1);
        }
    }
}

__global__ __launch_bounds__(256, 2) void qkv_gemm_kernel(
    const float* __restrict__ A, const float* __restrict__ W,
    const float* __restrict__ bias)
{
    tgemm2(A, W, bias, g_qkv, E3, Ee);
}

__global__ __launch_bounds__(256, 2) void proj_gemm_kernel(
    const float* __restrict__ W, const float* __restrict__ bias,
    float* __restrict__ C)
{
    tgemm2(g_attn, W, bias, C, Ee, Ee);
}

// ---------------------------------------------------------------------------
// Flash attention, tf32 mma — 256 thr (8 warps) = 128 queries per block,
// warp w owns rows qt*128 + w*16 .. +15. K/V tiles of 32 keys, cp.async
// double-buffered (prefetch 1 tile ahead). Compute math identical to the
// verified round-6 kernel; f2tf moved to fragment-load time.
// Smem (floats): KV stage s at s*4480 { K: 32x(68), V: 32x(72) };
// Q staged once into the same region before the KV loop, consumed to regs.
// ---------------------------------------------------------------------------
#define KVSTG 4480                       // 32*68 + 32*72 floats per stage
#define ATTN_SMEM_BYTES (2 * KVSTG * 4)  // 35840 B

__global__ __launch_bounds__(256) void attn_mma_kernel()
{
    extern __shared__ float ash[];

    const int qt = (Ss / 128 - 1) - blockIdx.x;   // heavy blocks first
    const int bh = blockIdx.y;
    const int b = bh >> 4, h = bh & 15;
    const int t = threadIdx.x, lane = t & 31, w = t >> 5;
    const int q = lane & 3, g = lane >> 2;

    const float* base   = g_qkv + (size_t)b * Ss * E3;
    const float* qbase  = base + (size_t)(qt * 128) * E3 + h * 64;
    const float* kvbase = base + Ee + h * 64;

    // ---- Stage Q (128 rows x 64 floats) via cp.async into smem, then regs
#pragma unroll
    for (int i = 0; i < 8; i++) {
        int idx = t + i * 256;            // 0..2047 float4 tasks
        int r = idx >> 4, c4 = idx & 15;
        cpa16(ash + r * 68 + c4 * 4, qbase + (size_t)r * E3 + c4 * 4);
    }
    cpa_commit();
    cpa_wait0();
    __syncthreads();

    unsigned aq[8][4];
#pragma unroll
    for (int kk = 0; kk < 8; kk++) {
        const float* p  = ash + (w * 16 + g) * 68 + kk * 8;
        const float* p8 = p + 8 * 68;
        aq[kk][0] = f2tf(0.125f * p[q]);
        aq[kk][1] = f2tf(0.125f * p8[q]);
        aq[kk][2] = f2tf(0.125f * p[q + 4]);
        aq[kk][3] = f2tf(0.125f * p8[q + 4]);
    }
    __syncthreads();   // Q region will be overwritten by KV stage 0

    float m0r = -1e30f, m1r = -1e30f, l0 = 0.f, l1 = 0.f;
    float o[8][4];
#pragma unroll
    for (int nf = 0; nf < 8; nf++)
#pragma unroll
        for (int r = 0; r < 4; r++) o[nf][r] = 0.f;

    const int r0 = qt * 128 + w * 16;                // warp's first query row
    const int myTiles = (r0 + 15) / 32 + 1;          // tiles this warp computes
    const int nkt = 4 * qt + 4;                      // tiles the block stages
    const int pg = (g >> 1) | ((g & 1) << 2);        // permuted key-in-frag

    // KV stage: 1024 float4 tasks (512 K + 512 V), 4 per thread
    auto stageKV = [&](int buf, int kt) {
        float* Ks = ash + buf * KVSTG;
        float* Vs = Ks + 32 * 68;
#pragma unroll
        for (int i = 0; i < 4; i++) {
            int idx = t + i * 256;        // 0..1023
            int r = (idx >> 4) & 31, c4 = idx & 15;
            const float* src = kvbase + (size_t)(kt * 32 + r) * E3 + c4 * 4;
            if (idx < 512)
                cpa16(Ks + r * 68 + c4 * 4, src);
            else
                cpa16(Vs + r * 72 + c4 * 4, src + Ee);
        }
    };

    stageKV(0, 0);
    cpa_commit();

    for (int kt = 0; kt < nkt; kt++) {
        if (kt + 1 < nkt) {
            stageKV((kt + 1) & 1, kt + 1);
            cpa_commit();
            cpa_wait1();
        } else {
            cpa_wait0();
        }
        __syncthreads();

        if (kt < myTiles) {
            const float* Ksf = ash + (kt & 1) * KVSTG;
            const float* Vsf = Ksf + 32 * 68;

            // S = Q @ K^T with permuted columns
            float s[4][4];
#pragma unroll
            for (int nf = 0; nf < 4; nf++)
#pragma unroll
                for (int r = 0; r < 4; r++) s[nf][r] = 0.f;

#pragma unroll
            for (int kk = 0; kk < 8; kk++) {
#pragma unroll
                for (int nf = 0; nf < 4; nf++) {
                    unsigned bb[2];
                    const float* kp = Ksf + (nf * 8 + pg) * 68 + kk * 8;
                    bb[0] = f2tf(kp[q]);
                    bb[1] = f2tf(kp[q + 4]);
                    mma_tf32(s[nf], aq[kk], bb);
                }
            }

            // Causal mask, only on this warp's last tile
            if (kt == myTiles - 1) {
                const int row0 = r0 + g;
#pragma unroll
                for (int nf = 0; nf < 4; nf++) {
                    int k0 = kt * 32 + nf * 8 + q;
                    int k1 = k0 + 4;
                    if (k0 > row0)     s[nf][0] = -1e30f;
                    if (k1 > row0)     s[nf][1] = -1e30f;
                    if (k0 > row0 + 8) s[nf][2] = -1e30f;
                    if (k1 > row0 + 8) s[nf][3] = -1e30f;
                }
            }

            // Online softmax
            float t0 = -1e30f, t1 = -1e30f;
#pragma unroll
            for (int nf = 0; nf < 4; nf++) {
                t0 = fmaxf(t0, fmaxf(s[nf][0], s[nf][1]));
                t1 = fmaxf(t1, fmaxf(s[nf][2], s[nf][3]));
            }
            t0 = fmaxf(t0, __shfl_xor_sync(0xffffffffu, t0, 1));
            t0 = fmaxf(t0, __shfl_xor_sync(0xffffffffu, t0, 2));
            t1 = fmaxf(t1, __shfl_xor_sync(0xffffffffu, t1, 1));
            t1 = fmaxf(t1, __shfl_xor_sync(0xffffffffu, t1, 2));

            float nm0 = fmaxf(m0r, t0), nm1 = fmaxf(m1r, t1);
            float cr0 = __expf(m0r - nm0), cr1 = __expf(m1r - nm1);
            m0r = nm0; m1r = nm1;
            l0 *= cr0; l1 *= cr1;
#pragma unroll
            for (int nf = 0; nf < 8; nf++) {
                o[nf][0] *= cr0; o[nf][1] *= cr0;
                o[nf][2] *= cr1; o[nf][3] *= cr1;
            }

            // P = exp(S - m); repack C-frag {c0,c2,c1,c3} as A-frag (tf32)
            unsigned p[4][4];
#pragma unroll
            for (int nf = 0; nf < 4; nf++) {
                float e0 = __expf(s[nf][0] - nm0);
                float e1 = __expf(s[nf][1] - nm0);
                float e2 = __expf(s[nf][2] - nm1);
                float e3 = __expf(s[nf][3] - nm1);
                l0 += e0 + e1;
                l1 += e2 + e3;
                p[nf][0] = f2tf(e0);
                p[nf][1] = f2tf(e2);
                p[nf][2] = f2tf(e1);
                p[nf][3] = f2tf(e3);
            }

            // O += P @ V
#pragma unroll
            for (int kk = 0; kk < 4; kk++) {
#pragma unroll
                for (int nf = 0; nf < 8; nf++) {
                    unsigned bb[2];
                    bb[0] = f2tf(Vsf[(kk * 8 + q) * 72 + nf * 8 + g]);
                    bb[1] = f2tf(Vsf[(kk * 8 + q + 4) * 72 + nf * 8 + g]);
                    mma_tf32(o[nf], p[kk], bb);
                }
            }
        }

        __syncthreads();   // all warps done reading before buffer reuse
    }

    l0 += __shfl_xor_sync(0xffffffffu, l0, 1);
    l0 += __shfl_xor_sync(0xffffffffu, l0, 2);
    l1 += __shfl_xor_sync(0xffffffffu, l1, 1);
    l1 += __shfl_xor_sync(0xffffffffu, l1, 2);
    const float i0 = 1.f / l0, i1 = 1.f / l1;

    float* orow0 = g_attn + ((size_t)b * Ss + r0 + g) * Ee + h * 64;
    float* orow1 = g_attn + ((size_t)b * Ss + r0 + g + 8) * Ee + h * 64;
#pragma unroll
    for (int nf = 0; nf < 8; nf++) {
        int c = nf * 8 + 2 * q;
        *(float2*)(orow0 + c) = make_float2(o[nf][0] * i0, o[nf][1] * i0);
        *(float2*)(orow1 + c) = make_float2(o[nf][2] * i1, o[nf][3] * i1);
    }
}

// ---------------------------------------------------------------------------
extern "C" void kernel_launch(void* const* d_in, const int* in_sizes, int n_in,
                              void* d_out, int out_size)
{
    const float* hs    = (const float*)d_in[0];
    const float* wqkv  = (const float*)d_in[1];
    const float* bqkv  = (const float*)d_in[2];
    const float* wproj = (const float*)d_in[3];
    const float* bproj = (const float*)d_in[4];
    float* out = (float*)d_out;

    static int smem_set = 0;
    if (!smem_set) {
        cudaFuncSetAttribute(qkv_gemm_kernel,
                             cudaFuncAttributeMaxDynamicSharedMemorySize, SMEM_BYTES);
        cudaFuncSetAttribute(proj_gemm_kernel,
                             cudaFuncAttributeMaxDynamicSharedMemorySize, SMEM_BYTES);
        smem_set = 1;
    }

    dim3 g1(E3 / 128, MM / 128);          // 24 x 32
    qkv_gemm_kernel<<<g1, 256, SMEM_BYTES>>>(hs, wqkv, bqkv);

    dim3 g2(Ss / 128, Bb * Hh);           // 16 x 32
    attn_mma_kernel<<<g2, 256, ATTN_SMEM_BYTES>>>();

    dim3 g3(Ee / 128, MM / 128);          // 8 x 32
    proj_gemm_kernel<<<g3, 256, SMEM_BYTES>>>(wproj, bproj, out);
}